// round 3
// baseline (speedup 1.0000x reference)
#include <cuda_runtime.h>

// ---------------------------------------------------------------------------
// 2-layer LSTM, B=256, H=512, T=512, F=1, 8 autoregressive future steps.
// Persistent kernel: 128 CTAs x 256 threads, weights resident in SMEM
// (f32x2-duplicated), cell state in registers, h exchanged via L2 with a
// monotonic-epoch grid barrier. FP32 via packed fma.rn.f32x2 (FFMA2).
// ---------------------------------------------------------------------------

#define NCTA 128
#define NTHR 256
#define BB   256          // batch
#define HH   512          // hidden
#define TT   512          // main timesteps
#define FUT  8
#define TCOLS (TT + FUT)  // 520 output columns

// ------------------------- device state ------------------------------------
__device__ __align__(16) float dH1[2][HH * BB];     // h1 double buffer, col-major [j][b]
__device__ __align__(16) float dH2[2][HH * BB];     // h2 double buffer
__device__ __align__(16) float dConst1[4 * HH * BB]; // x@Wih1^T + bih1 + bhh1, [row][b]
__device__ unsigned long long g_cnt   = 0;           // barrier arrivals (monotonic)
__device__ unsigned long long g_epoch = 0;           // barrier release epoch

// ------------------------- helpers -----------------------------------------
#define FMA2(acc, w, h) asm("fma.rn.f32x2 %0, %1, %2, %0;" : "+l"(acc) : "l"(w), "l"(h))

__device__ __forceinline__ unsigned long long pack2(float w) {
    unsigned long long r;
    asm("mov.b64 %0, {%1, %1};" : "=l"(r) : "f"(w));
    return r;
}
__device__ __forceinline__ float2 unpack2(unsigned long long v) {
    float2 r;
    asm("mov.b64 {%0, %1}, %2;" : "=f"(r.x), "=f"(r.y) : "l"(v));
    return r;
}
__device__ __forceinline__ float sigf(float x) {
    return 1.0f / (1.0f + __expf(-x));
}
__device__ __forceinline__ float tanh_s(float x) {
    float a = fabsf(x);
    float e = __expf(-2.0f * a);
    float t = (1.0f - e) / (1.0f + e);
    return x < 0.0f ? -t : t;
}

// Grid barrier: monotonic count/epoch, no resets (safe across graph replays).
__device__ __forceinline__ void gridbar() {
    __threadfence();
    __syncthreads();
    if (threadIdx.x == 0) {
        unsigned long long old  = atomicAdd(&g_cnt, 1ULL);
        unsigned long long need = old / NCTA + 1ULL;
        if ((old % NCTA) == (NCTA - 1)) {
            atomicExch(&g_epoch, need);
        } else {
            while (*((volatile unsigned long long*)&g_epoch) < need) { }
        }
    }
    __syncthreads();
    __threadfence();
}

// K=512 micro-GEMM: 16 gate-outputs (4 cols x 4 gates) x 4 batches per thread,
// packed f32x2 accumulation. w: SMEM duplicated weights, pre-offset by jt*2.
// hbuf: col-major [k][b] float, read via .cg (cross-CTA produced).
__device__ __forceinline__ void gemm512(const ulonglong2* __restrict__ w,
                                        const float* __restrict__ hbuf,
                                        int bg, unsigned long long acc[8]) {
    const longlong2* h = reinterpret_cast<const longlong2*>(hbuf) + bg;
#pragma unroll 8
    for (int k = 0; k < 512; ++k) {
        longlong2 hv = __ldcg(h + k * 64);       // 4 batch values (2x f32x2)
        ulonglong2 w01 = w[k * 8];               // gates 0,1 (dup)
        ulonglong2 w23 = w[k * 8 + 1];           // gates 2,3 (dup)
        unsigned long long h0 = (unsigned long long)hv.x;
        unsigned long long h1 = (unsigned long long)hv.y;
        FMA2(acc[0], w01.x, h0); FMA2(acc[1], w01.x, h1);
        FMA2(acc[2], w01.y, h0); FMA2(acc[3], w01.y, h1);
        FMA2(acc[4], w23.x, h0); FMA2(acc[5], w23.x, h1);
        FMA2(acc[6], w23.y, h0); FMA2(acc[7], w23.y, h1);
    }
}

// ------------------------- setup kernel -------------------------------------
// Precompute dConst1[row*B + b] = input_t[b]*Wih1[row] + bih1[row] + bhh1[row]
// and zero the "previous" h buffers (index 1) so step 0 reads zeros.
__global__ void setup_kernel(const float* __restrict__ input_t,
                             const float* __restrict__ Wih1,
                             const float* __restrict__ bih1,
                             const float* __restrict__ bhh1) {
    int idx = blockIdx.x * blockDim.x + threadIdx.x;
    if (idx < 4 * HH * BB) {
        int g = idx >> 8;        // row (0..2047)
        int b = idx & 255;
        dConst1[idx] = input_t[b] * Wih1[g] + bih1[g] + bhh1[g];
    }
    if (idx < HH * BB) {
        dH1[1][idx] = 0.0f;
        dH2[1][idx] = 0.0f;
    }
}

// ------------------------- main persistent kernel ---------------------------
__global__ void __launch_bounds__(NTHR, 1)
lstm_persist(const float* __restrict__ Wih1, const float* __restrict__ bih1,
             const float* __restrict__ Whh1, const float* __restrict__ bhh1,
             const float* __restrict__ Wih2, const float* __restrict__ bih2,
             const float* __restrict__ Whh2, const float* __restrict__ bhh2,
             const float* __restrict__ Wlin, const float* __restrict__ blin,
             float* __restrict__ OUT) {
    extern __shared__ __align__(16) unsigned long long smem_[];
    unsigned long long* sW1 = smem_;              // 8192  u64 (64 KB)
    unsigned long long* sW2 = smem_ + 8192;       // 16384 u64 (128 KB)
    float* sWlin = (float*)(smem_ + 8192 + 16384); // 512 floats
    float* sRed  = sWlin + 512;                    // 256 floats

    const int tid = threadIdx.x;
    const int jt  = tid & 3;     // which column of the CTA's 4
    const int bg  = tid >> 2;    // batch group (0..63), 4 batches each
    const int b0  = bg * 4;
    const int cb  = blockIdx.x * 4;  // first hidden column owned by this CTA
    const int col = cb + jt;

    // ---- load weight slices into SMEM (duplicated for f32x2), once ----
    // sW1 layout: [k][jj][g] as u64;  row = g*H + (cb+jj)
    for (int i = tid; i < 512 * 16; i += NTHR) {
        int k = i >> 4, r = i & 15, jj = r >> 2, g = r & 3;
        sW1[i] = pack2(Whh1[(g * HH + cb + jj) * HH + k]);
    }
    // sW2: K=1024 concat [Wih2 ; Whh2]
    for (int i = tid; i < 1024 * 16; i += NTHR) {
        int k = i >> 4, r = i & 15, jj = r >> 2, g = r & 3;
        int row = g * HH + cb + jj;
        float wv = (k < 512) ? Wih2[row * HH + k] : Whh2[row * HH + (k - 512)];
        sW2[i] = pack2(wv);
    }
    for (int i = tid; i < 512; i += NTHR) sWlin[i] = Wlin[i];
    __syncthreads();

    const float bl0 = blin[0];

    // cell state lives in registers for the whole sequence
    float c1[4] = {0.f, 0.f, 0.f, 0.f};
    float c2[4] = {0.f, 0.f, 0.f, 0.f};

    const ulonglong2* w1  = reinterpret_cast<const ulonglong2*>(sW1) + jt * 2;
    const ulonglong2* w2a = reinterpret_cast<const ulonglong2*>(sW2) + jt * 2;
    const ulonglong2* w2b = w2a + 4096;  // k = 512..1023 half

    for (int s = 0; s < TT + FUT; ++s) {
        const int cur = s & 1;
        const int prv = cur ^ 1;

        // ---- finalize OUT[:, s-1] for main steps (overlapped with P1) ----
        if (s >= 1 && s <= TT - 1) {
            int b  = blockIdx.x * 2 + (tid >> 7);
            int j0 = (tid & 127) * 4;
            const float* h2p = dH2[prv];   // (s-1)&1 == prv
            float p;
            p  = __ldcg(h2p + (j0 + 0) * BB + b) * sWlin[j0 + 0];
            p += __ldcg(h2p + (j0 + 1) * BB + b) * sWlin[j0 + 1];
            p += __ldcg(h2p + (j0 + 2) * BB + b) * sWlin[j0 + 2];
            p += __ldcg(h2p + (j0 + 3) * BB + b) * sWlin[j0 + 3];
            sRed[tid] = p;
            __syncthreads();
            for (int off = 64; off > 0; off >>= 1) {
                if ((tid & 127) < off) sRed[tid] += sRed[tid + off];
                __syncthreads();
            }
            if ((tid & 127) == 0) OUT[b * TCOLS + (s - 1)] = sRed[tid] + bl0;
            __syncthreads();
        }

        // ---------------- Phase 1: layer-1 cell ----------------
        {
            unsigned long long acc[8] = {0, 0, 0, 0, 0, 0, 0, 0};
            gemm512(w1, dH1[prv], bg, acc);

            float gt[4][4];
#pragma unroll
            for (int g = 0; g < 4; ++g) {
                float2 u0 = unpack2(acc[g * 2 + 0]);
                float2 u1 = unpack2(acc[g * 2 + 1]);
                gt[g][0] = u0.x; gt[g][1] = u0.y; gt[g][2] = u1.x; gt[g][3] = u1.y;
            }
            if (s < TT) {
#pragma unroll
                for (int g = 0; g < 4; ++g) {
                    const float4 c4 = *reinterpret_cast<const float4*>(
                        &dConst1[(g * HH + col) * BB + b0]);
                    gt[g][0] += c4.x; gt[g][1] += c4.y;
                    gt[g][2] += c4.z; gt[g][3] += c4.w;
                }
            } else {
                // autoregressive: x = out[:, s-1]
                float op[4];
#pragma unroll
                for (int p = 0; p < 4; ++p)
                    op[p] = __ldcg(&OUT[(b0 + p) * TCOLS + (s - 1)]);
#pragma unroll
                for (int g = 0; g < 4; ++g) {
                    int row  = g * HH + col;
                    float wi = Wih1[row];
                    float bb = bih1[row] + bhh1[row];
#pragma unroll
                    for (int p = 0; p < 4; ++p) gt[g][p] += op[p] * wi + bb;
                }
            }
            float ho[4];
#pragma unroll
            for (int p = 0; p < 4; ++p) {
                float iv = sigf(gt[0][p]);
                float fv = sigf(gt[1][p]);
                float gv = tanh_s(gt[2][p]);
                float ov = sigf(gt[3][p]);
                c1[p] = fv * c1[p] + iv * gv;
                ho[p] = ov * tanh_s(c1[p]);
            }
            *reinterpret_cast<float4*>(&dH1[cur][col * BB + b0]) =
                make_float4(ho[0], ho[1], ho[2], ho[3]);
        }
        gridbar();

        // ---------------- Phase 2: layer-2 cell ----------------
        {
            unsigned long long acc[8] = {0, 0, 0, 0, 0, 0, 0, 0};
            gemm512(w2a, dH1[cur], bg, acc);   // k 0..511   : h1(new)
            gemm512(w2b, dH2[prv], bg, acc);   // k 512..1023: h2(prev)

            float gt[4][4];
#pragma unroll
            for (int g = 0; g < 4; ++g) {
                float2 u0 = unpack2(acc[g * 2 + 0]);
                float2 u1 = unpack2(acc[g * 2 + 1]);
                gt[g][0] = u0.x; gt[g][1] = u0.y; gt[g][2] = u1.x; gt[g][3] = u1.y;
            }
#pragma unroll
            for (int g = 0; g < 4; ++g) {
                int row  = g * HH + col;
                float bb = bih2[row] + bhh2[row];
#pragma unroll
                for (int p = 0; p < 4; ++p) gt[g][p] += bb;
            }
            float ho[4];
#pragma unroll
            for (int p = 0; p < 4; ++p) {
                float iv = sigf(gt[0][p]);
                float fv = sigf(gt[1][p]);
                float gv = tanh_s(gt[2][p]);
                float ov = sigf(gt[3][p]);
                c2[p] = fv * c2[p] + iv * gv;
                ho[p] = ov * tanh_s(c2[p]);
            }
            *reinterpret_cast<float4*>(&dH2[cur][col * BB + b0]) =
                make_float4(ho[0], ho[1], ho[2], ho[3]);
        }
        gridbar();

        // ---- tail: finalize OUT[:, s] before the next (autoregressive) step
        if (s >= TT - 1) {
            int b  = blockIdx.x * 2 + (tid >> 7);
            int j0 = (tid & 127) * 4;
            const float* h2p = dH2[cur];
            float p;
            p  = __ldcg(h2p + (j0 + 0) * BB + b) * sWlin[j0 + 0];
            p += __ldcg(h2p + (j0 + 1) * BB + b) * sWlin[j0 + 1];
            p += __ldcg(h2p + (j0 + 2) * BB + b) * sWlin[j0 + 2];
            p += __ldcg(h2p + (j0 + 3) * BB + b) * sWlin[j0 + 3];
            sRed[tid] = p;
            __syncthreads();
            for (int off = 64; off > 0; off >>= 1) {
                if ((tid & 127) < off) sRed[tid] += sRed[tid + off];
                __syncthreads();
            }
            if ((tid & 127) == 0) OUT[b * TCOLS + s] = sRed[tid] + bl0;
            gridbar();
        }
    }
}

// ------------------------- launch -------------------------------------------
extern "C" void kernel_launch(void* const* d_in, const int* in_sizes, int n_in,
                              void* d_out, int out_size) {
    (void)in_sizes; (void)n_in; (void)out_size;
    const float* input_t = (const float*)d_in[0];
    // d_in[1] = y (shape-only, unused)
    const float* Wih1 = (const float*)d_in[2];
    const float* bih1 = (const float*)d_in[3];
    const float* Whh1 = (const float*)d_in[4];
    const float* bhh1 = (const float*)d_in[5];
    const float* Wih2 = (const float*)d_in[6];
    const float* bih2 = (const float*)d_in[7];
    const float* Whh2 = (const float*)d_in[8];
    const float* bhh2 = (const float*)d_in[9];
    const float* Wlin = (const float*)d_in[10];
    const float* blin = (const float*)d_in[11];
    float* OUT = (float*)d_out;

    setup_kernel<<<2048, 256>>>(input_t, Wih1, bih1, bhh1);

    size_t smem = (8192 + 16384) * sizeof(unsigned long long)
                + (512 + 256) * sizeof(float);  // 199,680 B
    cudaFuncSetAttribute(lstm_persist,
                         cudaFuncAttributeMaxDynamicSharedMemorySize, (int)smem);
    lstm_persist<<<NCTA, NTHR, smem>>>(Wih1, bih1, Whh1, bhh1,
                                       Wih2, bih2, Whh2, bhh2,
                                       Wlin, blin, OUT);
}

// round 4
// speedup vs baseline: 1.1682x; 1.1682x over previous
#include <cuda_runtime.h>

// ---------------------------------------------------------------------------
// 2-layer LSTM, B=256, H=512, T=512, F=1, +8 autoregressive steps.
// Persistent kernel, 128 CTAs x 256 threads.
// GEMM: thread tile 16 rows x 8 batches x K/8 k-slice; weights in SMEM
// row-pair packed (u64 = 2 rows, warp-broadcast across batch groups),
// h from L2 (1 read per (k,b) per CTA), FFMA2 (fma.rn.f32x2) accumulation,
// k-split resolved via halving shfl-xor tree. Cell state in registers.
// ---------------------------------------------------------------------------

#define NCTA 128
#define NTHR 256
#define BB   256
#define HH   512
#define TT   512
#define FUT  8
#define TCOLS (TT + FUT)

typedef unsigned long long u64;

// ------------------------- device state ------------------------------------
__device__ __align__(16) float dH1[2][HH * BB];      // [j][b] col-major
__device__ __align__(16) float dH2[2][HH * BB];
__device__ __align__(16) float dConst1[4 * HH * BB]; // x@Wih1^T + biases, [row][b]
__device__ u64 g_cnt   = 0;
__device__ u64 g_epoch = 0;

// ------------------------- helpers -----------------------------------------
#define FMA2(a, w, h) asm("fma.rn.f32x2 %0, %1, %2, %0;" : "+l"(a) : "l"(w), "l"(h))

__device__ __forceinline__ u64 add2(u64 a, u64 b) {
    u64 r; asm("add.rn.f32x2 %0, %1, %2;" : "=l"(r) : "l"(a), "l"(b)); return r;
}
__device__ __forceinline__ u64 packpair(float lo, float hi) {
    u64 r; asm("mov.b64 %0, {%1, %2};" : "=l"(r) : "f"(lo), "f"(hi)); return r;
}
__device__ __forceinline__ u64 dup2(float v) {
    u64 r; asm("mov.b64 %0, {%1, %1};" : "=l"(r) : "f"(v)); return r;
}
__device__ __forceinline__ float2 unpk(u64 v) {
    float2 r; asm("mov.b64 {%0, %1}, %2;" : "=f"(r.x), "=f"(r.y) : "l"(v)); return r;
}
__device__ __forceinline__ float sigf(float x) { return 1.0f / (1.0f + __expf(-x)); }
__device__ __forceinline__ float tanh_s(float x) {
    float a = fabsf(x);
    float e = __expf(-2.0f * a);
    float t = (1.0f - e) / (1.0f + e);
    return x < 0.0f ? -t : t;
}

// Grid barrier: monotonic count/epoch (graph-replay safe).
__device__ __forceinline__ void gridbar() {
    __threadfence();
    __syncthreads();
    if (threadIdx.x == 0) {
        u64 old  = atomicAdd(&g_cnt, 1ULL);
        u64 need = old / NCTA + 1ULL;
        if ((old % NCTA) == (NCTA - 1)) {
            atomicExch(&g_epoch, need);
        } else {
            while (*((volatile u64*)&g_epoch) < need) { }
        }
    }
    __syncthreads();
    __threadfence();
}

// ------------------------- micro-GEMM --------------------------------------
// Accumulate acc[bl*8+rp] += sum over thread's k-slice (k = i*8+ks, i<NI) of
// w[rp-pair](k) * h[b0+bl](k).  sW element: sW[rp*wstride + k] (u64 = 2 rows).
__device__ __forceinline__ void gemm_acc(const u64* __restrict__ sW, int wstride,
                                         const float* __restrict__ hbase,
                                         int ks, int b0, int NI, u64* acc) {
    const float* hp  = hbase + (size_t)ks * BB + b0;
    const int hstep  = 8 * BB;
    float4 pa[2], pb[2];
    pa[0] = __ldcg((const float4*)hp);
    pb[0] = __ldcg((const float4*)(hp + 4));
    pa[1] = __ldcg((const float4*)(hp + hstep));
    pb[1] = __ldcg((const float4*)(hp + hstep + 4));
    const u64* wp = sW + ks;
#pragma unroll 2
    for (int i = 0; i < NI; ++i) {
        float4 A = pa[i & 1], Bv = pb[i & 1];
        int ipf = (i + 2 < NI) ? (i + 2) : (NI - 1);  // clamp (redundant loads ok)
        const float* pn = hp + ipf * hstep;
        pa[i & 1] = __ldcg((const float4*)pn);
        pb[i & 1] = __ldcg((const float4*)(pn + 4));
        u64 w[8];
#pragma unroll
        for (int rp = 0; rp < 8; ++rp) w[rp] = wp[rp * wstride + i * 8];
        u64 hd[8];
        hd[0] = dup2(A.x);  hd[1] = dup2(A.y);  hd[2] = dup2(A.z);  hd[3] = dup2(A.w);
        hd[4] = dup2(Bv.x); hd[5] = dup2(Bv.y); hd[6] = dup2(Bv.z); hd[7] = dup2(Bv.w);
#pragma unroll
        for (int bl = 0; bl < 8; ++bl)
#pragma unroll
            for (int rp = 0; rp < 8; ++rp)
                FMA2(acc[bl * 8 + rp], w[rp], hd[bl]);
    }
}

// Halving tree-reduce across the 8 k-slice lanes (ks = lane bits [0:3)).
// acc linear idx = bl*8+rp. After: acc[0..8) = full sums for bl = ks, rp=0..7.
__device__ __forceinline__ void kreduce(u64* acc, int ks) {
    if (ks & 4) {
#pragma unroll
        for (int t = 0; t < 32; ++t) { u64 tmp = acc[t]; acc[t] = acc[t + 32]; acc[t + 32] = tmp; }
    }
#pragma unroll
    for (int t = 0; t < 32; ++t)
        acc[t] = add2(acc[t], __shfl_xor_sync(0xffffffffu, acc[t + 32], 4));
    if (ks & 2) {
#pragma unroll
        for (int t = 0; t < 16; ++t) { u64 tmp = acc[t]; acc[t] = acc[t + 16]; acc[t + 16] = tmp; }
    }
#pragma unroll
    for (int t = 0; t < 16; ++t)
        acc[t] = add2(acc[t], __shfl_xor_sync(0xffffffffu, acc[t + 16], 2));
    if (ks & 1) {
#pragma unroll
        for (int t = 0; t < 8; ++t) { u64 tmp = acc[t]; acc[t] = acc[t + 8]; acc[t + 8] = tmp; }
    }
#pragma unroll
    for (int t = 0; t < 8; ++t)
        acc[t] = add2(acc[t], __shfl_xor_sync(0xffffffffu, acc[t + 8], 1));
}

// ------------------------- setup kernel -------------------------------------
__global__ void setup_kernel(const float* __restrict__ input_t,
                             const float* __restrict__ Wih1,
                             const float* __restrict__ bih1,
                             const float* __restrict__ bhh1) {
    int idx = blockIdx.x * blockDim.x + threadIdx.x;
    if (idx < 4 * HH * BB) {
        int g = idx >> 8;
        int b = idx & 255;
        dConst1[idx] = input_t[b] * Wih1[g] + bih1[g] + bhh1[g];
    }
    if (idx < HH * BB) {
        dH1[1][idx] = 0.0f;
        dH2[1][idx] = 0.0f;
    }
}

// ------------------------- main persistent kernel ---------------------------
__global__ void __launch_bounds__(NTHR, 1)
lstm_persist(const float* __restrict__ Wih1, const float* __restrict__ bih1,
             const float* __restrict__ Whh1, const float* __restrict__ bhh1,
             const float* __restrict__ Wih2, const float* __restrict__ bih2,
             const float* __restrict__ Whh2, const float* __restrict__ bhh2,
             const float* __restrict__ Wlin, const float* __restrict__ blin,
             float* __restrict__ OUT) {
    extern __shared__ __align__(16) u64 smem_[];
    u64* sW1 = smem_;                       // 8 * 512  u64 (32 KB)
    u64* sW2 = smem_ + 8 * 512;             // 8 * 1024 u64 (64 KB)
    float* sWlin  = (float*)(sW2 + 8 * 1024);  // 512 floats
    float* sRed   = sWlin + 512;               // 256 floats
    float* sWih1r = sRed + 256;                // 16
    float* sBias1 = sWih1r + 16;               // 16
    float* sBias2 = sBias1 + 16;               // 16

    const int tid = threadIdx.x;
    const int ks  = tid & 7;          // k-slice lane
    const int bg  = tid >> 3;         // batch group 0..31 (8 batches each)
    const int b0  = bg * 8;
    const int cb  = blockIdx.x * 4;   // first hidden column owned by this CTA
    const int bfull = b0 + ks;        // owned batch after reduction

    // ---- load weight slices into SMEM (row-pair packed), once ----
    // sW1[rp*512 + k] = (Whh1[row_lo][k], Whh1[row_lo+1][k]);
    // row order: r_local = g*4 + cl  (g = gate, cl = local col), rp = r_local/2
    for (int i = tid; i < 8 * 512; i += NTHR) {
        int rp = i >> 9, k = i & 511;
        int g = rp >> 1, clb = (rp & 1) * 2;
        int row = g * HH + cb + clb;
        sW1[i] = packpair(Whh1[row * HH + k], Whh1[(row + 1) * HH + k]);
    }
    for (int i = tid; i < 8 * 1024; i += NTHR) {
        int rp = i >> 10, k = i & 1023;
        int g = rp >> 1, clb = (rp & 1) * 2;
        int row = g * HH + cb + clb;
        float lo, hi;
        if (k < 512) { lo = Wih2[row * HH + k];         hi = Wih2[(row + 1) * HH + k]; }
        else         { lo = Whh2[row * HH + (k - 512)]; hi = Whh2[(row + 1) * HH + (k - 512)]; }
        sW2[i] = packpair(lo, hi);
    }
    for (int i = tid; i < 512; i += NTHR) sWlin[i] = Wlin[i];
    if (tid < 16) {
        int g = tid >> 2, cl = tid & 3;
        int row = g * HH + cb + cl;
        sWih1r[tid] = Wih1[row];
        sBias1[tid] = bih1[row] + bhh1[row];
        sBias2[tid] = bih2[row] + bhh2[row];
    }
    __syncthreads();

    const float bl0 = blin[0];

    float c1[4] = {0.f, 0.f, 0.f, 0.f};
    float c2[4] = {0.f, 0.f, 0.f, 0.f};

    for (int s = 0; s < TT + FUT; ++s) {
        const int cur = s & 1;
        const int prv = cur ^ 1;

        // ---- finalize OUT[:, s-1] (overlapped; main steps only) ----
        if (s >= 1 && s <= TT - 1) {
            int b  = blockIdx.x * 2 + (tid >> 7);
            int j0 = (tid & 127) * 4;
            const float* h2p = dH2[prv];
            float p;
            p  = __ldcg(h2p + (j0 + 0) * BB + b) * sWlin[j0 + 0];
            p += __ldcg(h2p + (j0 + 1) * BB + b) * sWlin[j0 + 1];
            p += __ldcg(h2p + (j0 + 2) * BB + b) * sWlin[j0 + 2];
            p += __ldcg(h2p + (j0 + 3) * BB + b) * sWlin[j0 + 3];
            sRed[tid] = p;
            __syncthreads();
            for (int off = 64; off > 0; off >>= 1) {
                if ((tid & 127) < off) sRed[tid] += sRed[tid + off];
                __syncthreads();
            }
            if ((tid & 127) == 0) OUT[b * TCOLS + (s - 1)] = sRed[tid] + bl0;
            __syncthreads();
        }

        // ---------------- Phase 1: layer-1 cell ----------------
        {
            u64 acc[64];
#pragma unroll
            for (int t = 0; t < 64; ++t) acc[t] = 0ULL;
            gemm_acc(sW1, 512, dH1[prv], ks, b0, 64, acc);
            kreduce(acc, ks);

            float gt[16];
#pragma unroll
            for (int rp = 0; rp < 8; ++rp) {
                float2 p = unpk(acc[rp]);
                gt[2 * rp] = p.x; gt[2 * rp + 1] = p.y;
            }
            if (s < TT) {
#pragma unroll
                for (int r = 0; r < 16; ++r) {
                    int row = (r >> 2) * HH + cb + (r & 3);
                    gt[r] += dConst1[row * BB + bfull];
                }
            } else {
                float op = __ldcg(&OUT[bfull * TCOLS + (s - 1)]);
#pragma unroll
                for (int r = 0; r < 16; ++r)
                    gt[r] += op * sWih1r[r] + sBias1[r];
            }
#pragma unroll
            for (int cl = 0; cl < 4; ++cl) {
                float iv = sigf(gt[0 * 4 + cl]);
                float fv = sigf(gt[1 * 4 + cl]);
                float gv = tanh_s(gt[2 * 4 + cl]);
                float ov = sigf(gt[3 * 4 + cl]);
                c1[cl] = fv * c1[cl] + iv * gv;
                dH1[cur][(cb + cl) * BB + bfull] = ov * tanh_s(c1[cl]);
            }
        }
        gridbar();

        // ---------------- Phase 2: layer-2 cell ----------------
        {
            u64 acc[64];
#pragma unroll
            for (int t = 0; t < 64; ++t) acc[t] = 0ULL;
            gemm_acc(sW2,       1024, dH1[cur], ks, b0, 64, acc);  // k 0..511: h1(new)
            gemm_acc(sW2 + 512, 1024, dH2[prv], ks, b0, 64, acc);  // k 512..1023: h2(prev)
            kreduce(acc, ks);

            float gt[16];
#pragma unroll
            for (int rp = 0; rp < 8; ++rp) {
                float2 p = unpk(acc[rp]);
                gt[2 * rp] = p.x; gt[2 * rp + 1] = p.y;
            }
#pragma unroll
            for (int r = 0; r < 16; ++r) gt[r] += sBias2[r];
#pragma unroll
            for (int cl = 0; cl < 4; ++cl) {
                float iv = sigf(gt[0 * 4 + cl]);
                float fv = sigf(gt[1 * 4 + cl]);
                float gv = tanh_s(gt[2 * 4 + cl]);
                float ov = sigf(gt[3 * 4 + cl]);
                c2[cl] = fv * c2[cl] + iv * gv;
                dH2[cur][(cb + cl) * BB + bfull] = ov * tanh_s(c2[cl]);
            }
        }
        gridbar();

        // ---- tail: finalize OUT[:, s] before next autoregressive step ----
        if (s >= TT - 1) {
            int b  = blockIdx.x * 2 + (tid >> 7);
            int j0 = (tid & 127) * 4;
            const float* h2p = dH2[cur];
            float p;
            p  = __ldcg(h2p + (j0 + 0) * BB + b) * sWlin[j0 + 0];
            p += __ldcg(h2p + (j0 + 1) * BB + b) * sWlin[j0 + 1];
            p += __ldcg(h2p + (j0 + 2) * BB + b) * sWlin[j0 + 2];
            p += __ldcg(h2p + (j0 + 3) * BB + b) * sWlin[j0 + 3];
            sRed[tid] = p;
            __syncthreads();
            for (int off = 64; off > 0; off >>= 1) {
                if ((tid & 127) < off) sRed[tid] += sRed[tid + off];
                __syncthreads();
            }
            if ((tid & 127) == 0) OUT[b * TCOLS + s] = sRed[tid] + bl0;
            gridbar();
        }
    }
}

// ------------------------- launch -------------------------------------------
extern "C" void kernel_launch(void* const* d_in, const int* in_sizes, int n_in,
                              void* d_out, int out_size) {
    (void)in_sizes; (void)n_in; (void)out_size;
    const float* input_t = (const float*)d_in[0];
    const float* Wih1 = (const float*)d_in[2];
    const float* bih1 = (const float*)d_in[3];
    const float* Whh1 = (const float*)d_in[4];
    const float* bhh1 = (const float*)d_in[5];
    const float* Wih2 = (const float*)d_in[6];
    const float* bih2 = (const float*)d_in[7];
    const float* Whh2 = (const float*)d_in[8];
    const float* bhh2 = (const float*)d_in[9];
    const float* Wlin = (const float*)d_in[10];
    const float* blin = (const float*)d_in[11];
    float* OUT = (float*)d_out;

    setup_kernel<<<2048, 256>>>(input_t, Wih1, bih1, bhh1);

    size_t smem = (8 * 512 + 8 * 1024) * sizeof(u64)
                + (512 + 256 + 48) * sizeof(float);
    cudaFuncSetAttribute(lstm_persist,
                         cudaFuncAttributeMaxDynamicSharedMemorySize, (int)smem);
    lstm_persist<<<NCTA, NTHR, smem>>>(Wih1, bih1, Whh1, bhh1,
                                       Wih2, bih2, Whh2, bhh2,
                                       Wlin, blin, OUT);
}